// round 1
// baseline (speedup 1.0000x reference)
#include <cuda_runtime.h>

#define S_   24
#define B_   256
#define D_   1024
#define H_   16
#define DH_  64
#define L_   12
#define V_   32000
#define NTOK (S_ * B_)   // 6144

// Scratch (allocation-free rule: __device__ globals)
__device__ float g_x[NTOK * D_];
__device__ float g_q[NTOK * D_];
__device__ float g_k[NTOK * D_];
__device__ float g_v[NTOK * D_];

// ---------------------------------------------------------------------------
// Embedding: x[s,b,d] = token_embed[inputs[s,b], d] + pe[s, 0, d]
// ---------------------------------------------------------------------------
__global__ void __launch_bounds__(256) embed_kernel(
    const int* __restrict__ inp,
    const float* __restrict__ tok,
    const float* __restrict__ pe)
{
    int e4 = blockIdx.x * 256 + threadIdx.x;     // float4 index
    int e  = e4 * 4;                             // element index into [S,B,D]
    int n  = e / D_;                             // token row (s*B + b)
    int d  = e % D_;
    int s  = n / B_;
    int t  = inp[n];
    float4 a = *(const float4*)(tok + (size_t)t * D_ + d);
    float4 p = *(const float4*)(pe + (size_t)s * D_ + d);
    a.x += p.x; a.y += p.y; a.z += p.z; a.w += p.w;
    *(float4*)(g_x + e) = a;
}

// ---------------------------------------------------------------------------
// NT GEMM: C[m,n] = sum_k A[m,k] * B[n,k] + bias[n]
// A: [M, 1024] row-major, B: [N, 1024] row-major. All dims multiples of 128.
// 128x128 block tile, 8x8 per-thread tile, BK=8, 256 threads.
// ---------------------------------------------------------------------------
__device__ __forceinline__ void gemm_nt_128(
    const float* __restrict__ A, const float* __restrict__ B,
    const float* __restrict__ bias, float* __restrict__ C,
    int N, int bm, int bn)
{
    __shared__ float As[8][128];
    __shared__ float Bs[8][128];

    const int tid = threadIdx.x;
    const int lr  = tid >> 1;          // 0..127  row within tile
    const int lk  = (tid & 1) * 4;     // 0 or 4
    const int ty  = tid >> 4;          // 0..15
    const int tx  = tid & 15;          // 0..15

    const float* Ap = A + (size_t)(bm + lr) * D_ + lk;
    const float* Bp = B + (size_t)(bn + lr) * D_ + lk;

    float acc[8][8];
    #pragma unroll
    for (int i = 0; i < 8; i++)
        #pragma unroll
        for (int j = 0; j < 8; j++) acc[i][j] = 0.f;

    for (int k0 = 0; k0 < D_; k0 += 8) {
        float4 a4 = *(const float4*)(Ap + k0);
        float4 b4 = *(const float4*)(Bp + k0);
        As[lk + 0][lr] = a4.x; As[lk + 1][lr] = a4.y;
        As[lk + 2][lr] = a4.z; As[lk + 3][lr] = a4.w;
        Bs[lk + 0][lr] = b4.x; Bs[lk + 1][lr] = b4.y;
        Bs[lk + 2][lr] = b4.z; Bs[lk + 3][lr] = b4.w;
        __syncthreads();

        #pragma unroll
        for (int kk = 0; kk < 8; kk++) {
            float ar[8], br[8];
            *(float4*)(ar)     = *(const float4*)&As[kk][ty * 8];
            *(float4*)(ar + 4) = *(const float4*)&As[kk][ty * 8 + 4];
            *(float4*)(br)     = *(const float4*)&Bs[kk][tx * 8];
            *(float4*)(br + 4) = *(const float4*)&Bs[kk][tx * 8 + 4];
            #pragma unroll
            for (int i = 0; i < 8; i++)
                #pragma unroll
                for (int j = 0; j < 8; j++)
                    acc[i][j] = fmaf(ar[i], br[j], acc[i][j]);
        }
        __syncthreads();
    }

    #pragma unroll
    for (int i = 0; i < 8; i++) {
        int row = bm + ty * 8 + i;
        float* Crow = C + (size_t)row * N + bn + tx * 8;
        #pragma unroll
        for (int j = 0; j < 8; j += 4) {
            float4 o;
            o.x = acc[i][j + 0] + bias[bn + tx * 8 + j + 0];
            o.y = acc[i][j + 1] + bias[bn + tx * 8 + j + 1];
            o.z = acc[i][j + 2] + bias[bn + tx * 8 + j + 2];
            o.w = acc[i][j + 3] + bias[bn + tx * 8 + j + 3];
            *(float4*)(Crow + j) = o;
        }
    }
}

// QKV: fused via blockIdx.z (3 * 8 * 48 = 1152 blocks per launch)
__global__ void __launch_bounds__(256) qkv_gemm_kernel(
    const float* __restrict__ qw, const float* __restrict__ qb,
    const float* __restrict__ kw, const float* __restrict__ kb,
    const float* __restrict__ vw, const float* __restrict__ vb)
{
    const float* W; const float* bb; float* C;
    if (blockIdx.z == 0)      { W = qw; bb = qb; C = g_q; }
    else if (blockIdx.z == 1) { W = kw; bb = kb; C = g_k; }
    else                      { W = vw; bb = vb; C = g_v; }
    gemm_nt_128(g_x, W, bb, C, D_, blockIdx.y * 128, blockIdx.x * 128);
}

__global__ void __launch_bounds__(256) out_gemm_kernel(
    const float* __restrict__ W, const float* __restrict__ bias,
    float* __restrict__ C)
{
    gemm_nt_128(g_x, W, bias, C, V_, blockIdx.y * 128, blockIdx.x * 128);
}

// ---------------------------------------------------------------------------
// Attention: one block per (b, h). S=24, DH=64.
// scores = q k^T / sqrt(D); softmax over t; o = attn v; x += o (residual)
// ---------------------------------------------------------------------------
__global__ void __launch_bounds__(256) attn_kernel()
{
    __shared__ float qs[S_][DH_];
    __shared__ float ks[S_][DH_];
    __shared__ float vs[S_][DH_];
    __shared__ float sc[S_][S_];

    const int bh  = blockIdx.x;
    const int b   = bh >> 4;        // / H_
    const int h   = bh & 15;        // % H_
    const int tid = threadIdx.x;

    for (int idx = tid; idx < S_ * DH_; idx += 256) {
        int s = idx / DH_, d = idx % DH_;
        size_t off = ((size_t)s * B_ + b) * D_ + h * DH_ + d;
        qs[s][d] = g_q[off];
        ks[s][d] = g_k[off];
        vs[s][d] = g_v[off];
    }
    __syncthreads();

    const float scale = 0.03125f;   // 1/sqrt(1024)
    for (int idx = tid; idx < S_ * S_; idx += 256) {
        int s = idx / S_, t = idx % S_;
        float dot = 0.f;
        #pragma unroll
        for (int d = 0; d < DH_; d++) dot = fmaf(qs[s][d], ks[t][d], dot);
        sc[s][t] = dot * scale;
    }
    __syncthreads();

    if (tid < S_) {
        float m = -1e30f;
        #pragma unroll
        for (int t = 0; t < S_; t++) m = fmaxf(m, sc[tid][t]);
        float sum = 0.f;
        #pragma unroll
        for (int t = 0; t < S_; t++) {
            float e = expf(sc[tid][t] - m);
            sc[tid][t] = e;
            sum += e;
        }
        float inv = 1.f / sum;
        #pragma unroll
        for (int t = 0; t < S_; t++) sc[tid][t] *= inv;
    }
    __syncthreads();

    for (int idx = tid; idx < S_ * DH_; idx += 256) {
        int s = idx / DH_, d = idx % DH_;
        float o = 0.f;
        #pragma unroll
        for (int t = 0; t < S_; t++) o = fmaf(sc[s][t], vs[t][d], o);
        size_t off = ((size_t)s * B_ + b) * D_ + h * DH_ + d;
        g_x[off] += o;   // residual, in-place (each element owned by one thread)
    }
}

// ---------------------------------------------------------------------------
// Launch
// Input order: inputs, mask, token_embed, pe, qw, qb, kw, kb, vw, vb, out_w, out_b
// ---------------------------------------------------------------------------
extern "C" void kernel_launch(void* const* d_in, const int* in_sizes, int n_in,
                              void* d_out, int out_size)
{
    const int*   inp = (const int*)  d_in[0];
    // d_in[1] = mask (unused by reference)
    const float* tok = (const float*)d_in[2];
    const float* pe  = (const float*)d_in[3];
    const float* qw  = (const float*)d_in[4];
    const float* qb  = (const float*)d_in[5];
    const float* kw  = (const float*)d_in[6];
    const float* kb  = (const float*)d_in[7];
    const float* vw  = (const float*)d_in[8];
    const float* vb  = (const float*)d_in[9];
    const float* ow  = (const float*)d_in[10];
    const float* ob  = (const float*)d_in[11];
    float* out = (float*)d_out;

    embed_kernel<<<NTOK * D_ / 4 / 256, 256>>>(inp, tok, pe);

    for (int l = 0; l < L_; l++) {
        const size_t wo = (size_t)l * D_ * D_;
        const size_t bo = (size_t)l * D_;
        qkv_gemm_kernel<<<dim3(D_ / 128, NTOK / 128, 3), 256>>>(
            qw + wo, qb + bo, kw + wo, kb + bo, vw + wo, vb + bo);
        attn_kernel<<<B_ * H_, 256>>>();
    }

    out_gemm_kernel<<<dim3(V_ / 128, NTOK / 128), 256>>>(ow, ob, out);
}

// round 2
// speedup vs baseline: 2.2229x; 2.2229x over previous
#include <cuda_runtime.h>
#include <cstdint>

#define S_   24
#define B_   256
#define D_   1024
#define H_   16
#define DH_  64
#define L_   12
#define V_   32000
#define NTOK (S_ * B_)   // 6144

// Scratch (allocation-free rule: __device__ globals)
__device__ float g_x[NTOK * D_];
__device__ float g_q[NTOK * D_];
__device__ float g_k[NTOK * D_];
__device__ float g_v[NTOK * D_];

// ---------------------------------------------------------------------------
// Embedding
// ---------------------------------------------------------------------------
__global__ void __launch_bounds__(256) embed_kernel(
    const int* __restrict__ inp,
    const float* __restrict__ tok,
    const float* __restrict__ pe)
{
    int e4 = blockIdx.x * 256 + threadIdx.x;
    int e  = e4 * 4;
    int n  = e / D_;
    int d  = e % D_;
    int s  = n / B_;
    int t  = inp[n];
    float4 a = *(const float4*)(tok + (size_t)t * D_ + d);
    float4 p = *(const float4*)(pe + (size_t)s * D_ + d);
    a.x += p.x; a.y += p.y; a.z += p.z; a.w += p.w;
    *(float4*)(g_x + e) = a;
}

// ---------------------------------------------------------------------------
// TF32 tensor-core NT GEMM: C[m,n] = sum_k A[m,k]*B[n,k] + bias[n]
// A:[M,1024] row-major, B:[N,1024] row-major. M,N multiples of 128.
// 128x128 block tile, BK=16 double-buffered smem, 8 warps @ 64x32 warp tiles,
// mma.sync.m16n8k8.tf32 with explicit RNA rounding.
// ---------------------------------------------------------------------------
#define BM 128
#define BN 128
#define BK 16
#define PAD 8
#define BMP (BM + PAD)
#define BNP (BN + PAD)
#define KTILES (D_ / BK)   // 64

__device__ __forceinline__ uint32_t f2tf(float x) {
    uint32_t y;
    asm("cvt.rna.tf32.f32 %0, %1;" : "=r"(y) : "f"(x));
    return y;
}

__device__ __forceinline__ void mma_tf32(float* d, const uint32_t* a, const uint32_t* b) {
    asm volatile(
        "mma.sync.aligned.m16n8k8.row.col.f32.tf32.tf32.f32 "
        "{%0,%1,%2,%3}, {%4,%5,%6,%7}, {%8,%9}, {%0,%1,%2,%3};"
        : "+f"(d[0]), "+f"(d[1]), "+f"(d[2]), "+f"(d[3])
        : "r"(a[0]), "r"(a[1]), "r"(a[2]), "r"(a[3]), "r"(b[0]), "r"(b[1]));
}

__device__ __forceinline__ void gemm_tf32(
    const float* __restrict__ A, const float* __restrict__ B,
    const float* __restrict__ bias, float* __restrict__ C,
    int N, int bm, int bn)
{
    __shared__ uint32_t As[2][BK][BMP];
    __shared__ uint32_t Bs[2][BK][BNP];

    const int tid  = threadIdx.x;
    const int wid  = tid >> 5;
    const int lane = tid & 31;
    const int grp  = lane >> 2;      // 0..7
    const int tig  = lane & 3;       // 0..3
    const int wm   = (wid >> 2) * 64;  // 0 or 64
    const int wn   = (wid & 3) * 32;   // 0,32,64,96

    const int lr = tid >> 1;         // 0..127 (tile row)
    const int lk = (tid & 1) * 8;    // 0 or 8 (k offset)

    const float* Ap = A + (size_t)(bm + lr) * D_ + lk;
    const float* Bp = B + (size_t)(bn + lr) * D_ + lk;

    float acc[4][4][4];
    #pragma unroll
    for (int i = 0; i < 4; i++)
        #pragma unroll
        for (int j = 0; j < 4; j++)
            #pragma unroll
            for (int c = 0; c < 4; c++) acc[i][j][c] = 0.f;

    float4 ra0, ra1, rb0, rb1;

    // prologue: tile 0
    ra0 = *(const float4*)(Ap);     ra1 = *(const float4*)(Ap + 4);
    rb0 = *(const float4*)(Bp);     rb1 = *(const float4*)(Bp + 4);

    As[0][lk+0][lr] = f2tf(ra0.x); As[0][lk+1][lr] = f2tf(ra0.y);
    As[0][lk+2][lr] = f2tf(ra0.z); As[0][lk+3][lr] = f2tf(ra0.w);
    As[0][lk+4][lr] = f2tf(ra1.x); As[0][lk+5][lr] = f2tf(ra1.y);
    As[0][lk+6][lr] = f2tf(ra1.z); As[0][lk+7][lr] = f2tf(ra1.w);
    Bs[0][lk+0][lr] = f2tf(rb0.x); Bs[0][lk+1][lr] = f2tf(rb0.y);
    Bs[0][lk+2][lr] = f2tf(rb0.z); Bs[0][lk+3][lr] = f2tf(rb0.w);
    Bs[0][lk+4][lr] = f2tf(rb1.x); Bs[0][lk+5][lr] = f2tf(rb1.y);
    Bs[0][lk+6][lr] = f2tf(rb1.z); Bs[0][lk+7][lr] = f2tf(rb1.w);
    __syncthreads();

    for (int t = 0; t < KTILES; t++) {
        const int cur = t & 1;
        const int nxt = cur ^ 1;

        if (t + 1 < KTILES) {
            const float* Ap2 = Ap + (t + 1) * BK;
            const float* Bp2 = Bp + (t + 1) * BK;
            ra0 = *(const float4*)(Ap2);  ra1 = *(const float4*)(Ap2 + 4);
            rb0 = *(const float4*)(Bp2);  rb1 = *(const float4*)(Bp2 + 4);
        }

        #pragma unroll
        for (int ks = 0; ks < BK; ks += 8) {
            uint32_t af[4][4], bf[4][2];
            #pragma unroll
            for (int i = 0; i < 4; i++) {
                int m = wm + i * 16 + grp;
                af[i][0] = As[cur][ks + tig][m];
                af[i][1] = As[cur][ks + tig][m + 8];
                af[i][2] = As[cur][ks + tig + 4][m];
                af[i][3] = As[cur][ks + tig + 4][m + 8];
            }
            #pragma unroll
            for (int j = 0; j < 4; j++) {
                int n = wn + j * 8 + grp;
                bf[j][0] = Bs[cur][ks + tig][n];
                bf[j][1] = Bs[cur][ks + tig + 4][n];
            }
            #pragma unroll
            for (int i = 0; i < 4; i++)
                #pragma unroll
                for (int j = 0; j < 4; j++)
                    mma_tf32(acc[i][j], af[i], bf[j]);
        }

        if (t + 1 < KTILES) {
            As[nxt][lk+0][lr] = f2tf(ra0.x); As[nxt][lk+1][lr] = f2tf(ra0.y);
            As[nxt][lk+2][lr] = f2tf(ra0.z); As[nxt][lk+3][lr] = f2tf(ra0.w);
            As[nxt][lk+4][lr] = f2tf(ra1.x); As[nxt][lk+5][lr] = f2tf(ra1.y);
            As[nxt][lk+6][lr] = f2tf(ra1.z); As[nxt][lk+7][lr] = f2tf(ra1.w);
            Bs[nxt][lk+0][lr] = f2tf(rb0.x); Bs[nxt][lk+1][lr] = f2tf(rb0.y);
            Bs[nxt][lk+2][lr] = f2tf(rb0.z); Bs[nxt][lk+3][lr] = f2tf(rb0.w);
            Bs[nxt][lk+4][lr] = f2tf(rb1.x); Bs[nxt][lk+5][lr] = f2tf(rb1.y);
            Bs[nxt][lk+6][lr] = f2tf(rb1.z); Bs[nxt][lk+7][lr] = f2tf(rb1.w);
        }
        __syncthreads();
    }

    // epilogue
    #pragma unroll
    for (int i = 0; i < 4; i++) {
        int row0 = bm + wm + i * 16 + grp;
        #pragma unroll
        for (int j = 0; j < 4; j++) {
            int col = bn + wn + j * 8 + tig * 2;
            float b0 = bias[col], b1 = bias[col + 1];
            float2 v0 = { acc[i][j][0] + b0, acc[i][j][1] + b1 };
            float2 v1 = { acc[i][j][2] + b0, acc[i][j][3] + b1 };
            *(float2*)(C + (size_t)row0 * N + col)       = v0;
            *(float2*)(C + (size_t)(row0 + 8) * N + col) = v1;
        }
    }
}

__global__ void __launch_bounds__(256, 2) qkv_gemm_kernel(
    const float* __restrict__ qw, const float* __restrict__ qb,
    const float* __restrict__ kw, const float* __restrict__ kb,
    const float* __restrict__ vw, const float* __restrict__ vb)
{
    const float* W; const float* bb; float* C;
    if (blockIdx.z == 0)      { W = qw; bb = qb; C = g_q; }
    else if (blockIdx.z == 1) { W = kw; bb = kb; C = g_k; }
    else                      { W = vw; bb = vb; C = g_v; }
    gemm_tf32(g_x, W, bb, C, D_, blockIdx.y * BM, blockIdx.x * BN);
}

__global__ void __launch_bounds__(256, 2) out_gemm_kernel(
    const float* __restrict__ W, const float* __restrict__ bias,
    float* __restrict__ C)
{
    gemm_tf32(g_x, W, bias, C, V_, blockIdx.y * BM, blockIdx.x * BN);
}

// ---------------------------------------------------------------------------
// Attention: one block per (b, h). S=24, DH=64. Fused residual add.
// ---------------------------------------------------------------------------
__global__ void __launch_bounds__(256) attn_kernel()
{
    __shared__ float qs[S_][DH_];
    __shared__ float ks[S_][DH_];
    __shared__ float vs[S_][DH_];
    __shared__ float sc[S_][S_];

    const int bh  = blockIdx.x;
    const int b   = bh >> 4;
    const int h   = bh & 15;
    const int tid = threadIdx.x;

    for (int idx = tid; idx < S_ * DH_; idx += 256) {
        int s = idx / DH_, d = idx % DH_;
        size_t off = ((size_t)s * B_ + b) * D_ + h * DH_ + d;
        qs[s][d] = g_q[off];
        ks[s][d] = g_k[off];
        vs[s][d] = g_v[off];
    }
    __syncthreads();

    const float scale = 0.03125f;   // 1/sqrt(1024)
    for (int idx = tid; idx < S_ * S_; idx += 256) {
        int s = idx / S_, t = idx % S_;
        float dot = 0.f;
        #pragma unroll
        for (int d = 0; d < DH_; d++) dot = fmaf(qs[s][d], ks[t][d], dot);
        sc[s][t] = dot * scale;
    }
    __syncthreads();

    if (tid < S_) {
        float m = -1e30f;
        #pragma unroll
        for (int t = 0; t < S_; t++) m = fmaxf(m, sc[tid][t]);
        float sum = 0.f;
        #pragma unroll
        for (int t = 0; t < S_; t++) {
            float e = expf(sc[tid][t] - m);
            sc[tid][t] = e;
            sum += e;
        }
        float inv = 1.f / sum;
        #pragma unroll
        for (int t = 0; t < S_; t++) sc[tid][t] *= inv;
    }
    __syncthreads();

    for (int idx = tid; idx < S_ * DH_; idx += 256) {
        int s = idx / DH_, d = idx % DH_;
        float o = 0.f;
        #pragma unroll
        for (int t = 0; t < S_; t++) o = fmaf(sc[s][t], vs[t][d], o);
        size_t off = ((size_t)s * B_ + b) * D_ + h * DH_ + d;
        g_x[off] += o;
    }
}

// ---------------------------------------------------------------------------
// Launch
// ---------------------------------------------------------------------------
extern "C" void kernel_launch(void* const* d_in, const int* in_sizes, int n_in,
                              void* d_out, int out_size)
{
    const int*   inp = (const int*)  d_in[0];
    const float* tok = (const float*)d_in[2];
    const float* pe  = (const float*)d_in[3];
    const float* qw  = (const float*)d_in[4];
    const float* qb  = (const float*)d_in[5];
    const float* kw  = (const float*)d_in[6];
    const float* kb  = (const float*)d_in[7];
    const float* vw  = (const float*)d_in[8];
    const float* vb  = (const float*)d_in[9];
    const float* ow  = (const float*)d_in[10];
    const float* ob  = (const float*)d_in[11];
    float* out = (float*)d_out;

    embed_kernel<<<NTOK * D_ / 4 / 256, 256>>>(inp, tok, pe);

    for (int l = 0; l < L_; l++) {
        const size_t wo = (size_t)l * D_ * D_;
        const size_t bo = (size_t)l * D_;
        qkv_gemm_kernel<<<dim3(D_ / BN, NTOK / BM, 3), 256>>>(
            qw + wo, qb + bo, kw + wo, kb + bo, vw + wo, vb + bo);
        attn_kernel<<<B_ * H_, 256>>>();
    }

    out_gemm_kernel<<<dim3(V_ / BN, NTOK / BM), 256>>>(ow, ob, out);
}